// round 1
// baseline (speedup 1.0000x reference)
#include <cuda_runtime.h>
#include <cuda_bf16.h>
#include <math.h>

// Problem constants
#define BATCH 4
#define SLEN  2048
#define EMB   1024
#define QKVF  3072   // 3*EMB

// Scratch buffers (allocation-free rule: __device__ globals)
__device__ float g_qkv[(size_t)BATCH * SLEN * QKVF];   // [B,S,3E]  96 MB
__device__ float g_att[(size_t)BATCH * SLEN * SLEN];   // [B,S,S]   64 MB
__device__ float g_ctx[(size_t)BATCH * SLEN * EMB];    // [B,S,E]   32 MB

// ---------------------------------------------------------------------------
// GEMM NT: C[m,n] = alpha * sum_k A[m,k]*B[n,k] + bias[n]
// A: M x K row-major (stride lda), B: N x K row-major (stride ldb)
// Batched via blockIdx.z with element strides sA/sB/sC.
// All of M, N assumed multiples of 128; K multiple of 8; pointers 16B aligned.
// ---------------------------------------------------------------------------
__global__ void __launch_bounds__(256)
gemm_nt_kernel(const float* __restrict__ A, const float* __restrict__ B,
               float* __restrict__ C, int K, int lda, int ldb, int ldc,
               size_t sA, size_t sB, size_t sC,
               const float* __restrict__ bias, float alpha)
{
    __shared__ float As[8][132];
    __shared__ float Bs[8][132];

    const int bz = blockIdx.z;
    const float* Ab = A + (size_t)bz * sA + (size_t)blockIdx.y * 128 * lda;
    const float* Bb = B + (size_t)bz * sB + (size_t)blockIdx.x * 128 * ldb;
    float*       Cb = C + (size_t)bz * sC + (size_t)blockIdx.y * 128 * ldc
                        + (size_t)blockIdx.x * 128;

    const int tid   = threadIdx.x;
    const int lrow  = tid >> 1;         // 0..127: row of A/B tile to load
    const int lcol4 = (tid & 1) * 4;    // 0 or 4: k sub-offset
    const int tx    = tid & 15;         // 0..15 -> output cols tx*8..
    const int ty    = tid >> 4;         // 0..15 -> output rows ty*8..

    float acc[8][8];
    #pragma unroll
    for (int i = 0; i < 8; i++)
        #pragma unroll
        for (int j = 0; j < 8; j++) acc[i][j] = 0.0f;

    for (int k0 = 0; k0 < K; k0 += 8) {
        float4 av = *(const float4*)(Ab + (size_t)lrow * lda + k0 + lcol4);
        float4 bv = *(const float4*)(Bb + (size_t)lrow * ldb + k0 + lcol4);
        As[lcol4 + 0][lrow] = av.x; As[lcol4 + 1][lrow] = av.y;
        As[lcol4 + 2][lrow] = av.z; As[lcol4 + 3][lrow] = av.w;
        Bs[lcol4 + 0][lrow] = bv.x; Bs[lcol4 + 1][lrow] = bv.y;
        Bs[lcol4 + 2][lrow] = bv.z; Bs[lcol4 + 3][lrow] = bv.w;
        __syncthreads();

        #pragma unroll
        for (int kk = 0; kk < 8; kk++) {
            float4 a0 = *(const float4*)&As[kk][ty * 8];
            float4 a1 = *(const float4*)&As[kk][ty * 8 + 4];
            float4 b0 = *(const float4*)&Bs[kk][tx * 8];
            float4 b1 = *(const float4*)&Bs[kk][tx * 8 + 4];
            float ar[8] = {a0.x, a0.y, a0.z, a0.w, a1.x, a1.y, a1.z, a1.w};
            float br[8] = {b0.x, b0.y, b0.z, b0.w, b1.x, b1.y, b1.z, b1.w};
            #pragma unroll
            for (int i = 0; i < 8; i++)
                #pragma unroll
                for (int j = 0; j < 8; j++)
                    acc[i][j] = fmaf(ar[i], br[j], acc[i][j]);
        }
        __syncthreads();
    }

    #pragma unroll
    for (int i = 0; i < 8; i++) {
        float* cr = Cb + (size_t)(ty * 8 + i) * ldc + tx * 8;
        #pragma unroll
        for (int j = 0; j < 8; j++) {
            float v = acc[i][j] * alpha;
            if (bias) v += bias[blockIdx.x * 128 + tx * 8 + j];
            cr[j] = v;
        }
    }
}

// ---------------------------------------------------------------------------
// GEMM NN: C[m,n] = alpha * sum_k A[m,k]*B[k,n]
// A: M x K row-major (stride lda), B: K x N row-major (stride ldb)
// ---------------------------------------------------------------------------
__global__ void __launch_bounds__(256)
gemm_nn_kernel(const float* __restrict__ A, const float* __restrict__ B,
               float* __restrict__ C, int K, int lda, int ldb, int ldc,
               size_t sA, size_t sB, size_t sC, float alpha)
{
    __shared__ float As[8][132];
    __shared__ float Bs[8][132];

    const int bz = blockIdx.z;
    const float* Ab = A + (size_t)bz * sA + (size_t)blockIdx.y * 128 * lda;
    const float* Bb = B + (size_t)bz * sB + (size_t)blockIdx.x * 128;
    float*       Cb = C + (size_t)bz * sC + (size_t)blockIdx.y * 128 * ldc
                        + (size_t)blockIdx.x * 128;

    const int tid   = threadIdx.x;
    const int larow  = tid >> 1;        // A tile load: row 0..127
    const int lacol4 = (tid & 1) * 4;   // k sub-offset 0/4
    const int lbrow  = tid >> 5;        // B tile load: k-row 0..7
    const int lbcol4 = (tid & 31) * 4;  // n offset 0..124
    const int tx    = tid & 15;
    const int ty    = tid >> 4;

    float acc[8][8];
    #pragma unroll
    for (int i = 0; i < 8; i++)
        #pragma unroll
        for (int j = 0; j < 8; j++) acc[i][j] = 0.0f;

    for (int k0 = 0; k0 < K; k0 += 8) {
        float4 av = *(const float4*)(Ab + (size_t)larow * lda + k0 + lacol4);
        float4 bv = *(const float4*)(Bb + (size_t)(k0 + lbrow) * ldb + lbcol4);
        As[lacol4 + 0][larow] = av.x; As[lacol4 + 1][larow] = av.y;
        As[lacol4 + 2][larow] = av.z; As[lacol4 + 3][larow] = av.w;
        *(float4*)&Bs[lbrow][lbcol4] = bv;
        __syncthreads();

        #pragma unroll
        for (int kk = 0; kk < 8; kk++) {
            float4 a0 = *(const float4*)&As[kk][ty * 8];
            float4 a1 = *(const float4*)&As[kk][ty * 8 + 4];
            float4 b0 = *(const float4*)&Bs[kk][tx * 8];
            float4 b1 = *(const float4*)&Bs[kk][tx * 8 + 4];
            float ar[8] = {a0.x, a0.y, a0.z, a0.w, a1.x, a1.y, a1.z, a1.w};
            float br[8] = {b0.x, b0.y, b0.z, b0.w, b1.x, b1.y, b1.z, b1.w};
            #pragma unroll
            for (int i = 0; i < 8; i++)
                #pragma unroll
                for (int j = 0; j < 8; j++)
                    acc[i][j] = fmaf(ar[i], br[j], acc[i][j]);
        }
        __syncthreads();
    }

    #pragma unroll
    for (int i = 0; i < 8; i++) {
        float* cr = Cb + (size_t)(ty * 8 + i) * ldc + tx * 8;
        #pragma unroll
        for (int j = 0; j < 8; j++)
            cr[j] = acc[i][j] * alpha;
    }
}

// ---------------------------------------------------------------------------
// Masked softmax over each row of att [B*S, S], in place.
// One block (256 threads) per row; 8 elements per thread.
// ---------------------------------------------------------------------------
__global__ void __launch_bounds__(256)
softmax_mask_kernel(float* __restrict__ att, const int* __restrict__ mask)
{
    const size_t row = blockIdx.x;
    float*       a = att  + row * (size_t)SLEN;
    const int*   m = mask + row * (size_t)SLEN;
    const int tid = threadIdx.x;

    float v[8];
    float lmax = -INFINITY;
    #pragma unroll
    for (int i = 0; i < 8; i++) {
        int c = tid + i * 256;
        float x = a[c];
        if (m[c] == 0) x = -INFINITY;
        v[i] = x;
        lmax = fmaxf(lmax, x);
    }

    __shared__ float smax[8];
    __shared__ float ssum[8];

    // block max
    #pragma unroll
    for (int o = 16; o > 0; o >>= 1)
        lmax = fmaxf(lmax, __shfl_xor_sync(0xffffffffu, lmax, o));
    if ((tid & 31) == 0) smax[tid >> 5] = lmax;
    __syncthreads();
    float gmax = fmaxf(fmaxf(fmaxf(smax[0], smax[1]), fmaxf(smax[2], smax[3])),
                       fmaxf(fmaxf(smax[4], smax[5]), fmaxf(smax[6], smax[7])));

    // exp + block sum
    float lsum = 0.0f;
    #pragma unroll
    for (int i = 0; i < 8; i++) {
        v[i] = __expf(v[i] - gmax);
        lsum += v[i];
    }
    #pragma unroll
    for (int o = 16; o > 0; o >>= 1)
        lsum += __shfl_xor_sync(0xffffffffu, lsum, o);
    if ((tid & 31) == 0) ssum[tid >> 5] = lsum;
    __syncthreads();
    float gsum = (ssum[0] + ssum[1]) + (ssum[2] + ssum[3])
               + (ssum[4] + ssum[5]) + (ssum[6] + ssum[7]);

    float inv = 1.0f / gsum;
    #pragma unroll
    for (int i = 0; i < 8; i++)
        a[tid + i * 256] = v[i] * inv;
}

// ---------------------------------------------------------------------------
// Launch: 5-stage pipeline, all on the capture stream.
// ---------------------------------------------------------------------------
extern "C" void kernel_launch(void* const* d_in, const int* in_sizes, int n_in,
                              void* d_out, int out_size)
{
    const float* X     = (const float*)d_in[0];  // [4,2048,1024]
    const int*   mask  = (const int*)  d_in[1];  // [4,2048,2048]
    const float* W_qkv = (const float*)d_in[2];  // [3072,1024]
    const float* b_qkv = (const float*)d_in[3];  // [3072]
    const float* W_out = (const float*)d_in[4];  // [1024,1024]
    const float* b_out = (const float*)d_in[5];  // [1024]
    float*       out   = (float*)d_out;          // [4,2048,1024]

    float *qkv, *att, *ctx;
    cudaGetSymbolAddress((void**)&qkv, g_qkv);
    cudaGetSymbolAddress((void**)&att, g_att);
    cudaGetSymbolAddress((void**)&ctx, g_ctx);

    const float scale = 1.0f / 32.0f;  // 1/sqrt(1024)

    // 1) qkv[BS,3072] = X[BS,1024] @ W_qkv^T + b_qkv
    gemm_nt_kernel<<<dim3(QKVF / 128, (BATCH * SLEN) / 128, 1), 256>>>(
        X, W_qkv, qkv, EMB, EMB, EMB, QKVF, 0, 0, 0, b_qkv, 1.0f);

    // 2) att[b] = Q_b @ K_b^T * scale  (Q at col 0, K at col 1024 of qkv)
    gemm_nt_kernel<<<dim3(SLEN / 128, SLEN / 128, BATCH), 256>>>(
        qkv, qkv + EMB, att, EMB, QKVF, QKVF, SLEN,
        (size_t)SLEN * QKVF, (size_t)SLEN * QKVF, (size_t)SLEN * SLEN,
        nullptr, scale);

    // 3) masked softmax rows
    softmax_mask_kernel<<<BATCH * SLEN, 256>>>(att, mask);

    // 4) ctx[b] = att_b @ V_b  (V at col 2048 of qkv)
    gemm_nn_kernel<<<dim3(EMB / 128, SLEN / 128, BATCH), 256>>>(
        att, qkv + 2 * EMB, ctx, SLEN, SLEN, QKVF, EMB,
        (size_t)SLEN * SLEN, (size_t)SLEN * QKVF, (size_t)SLEN * EMB, 1.0f);

    // 5) out[BS,1024] = ctx[BS,1024] @ W_out^T + b_out
    gemm_nt_kernel<<<dim3(EMB / 128, (BATCH * SLEN) / 128, 1), 256>>>(
        ctx, W_out, out, EMB, EMB, EMB, EMB, 0, 0, 0, b_out, 1.0f);
}

// round 4
// speedup vs baseline: 2.6868x; 2.6868x over previous
#include <cuda_runtime.h>
#include <cuda_bf16.h>
#include <math.h>
#include <stdint.h>

// Problem constants
#define BATCH 4
#define SLEN  2048
#define EMB   1024
#define QKVF  3072

// ---------------------------------------------------------------------------
// Device scratch (allocation-free rule: __device__ globals)
// ---------------------------------------------------------------------------
__device__ __align__(256) __nv_bfloat16 g_Xh[(size_t)BATCH*SLEN*EMB];
__device__ __align__(256) __nv_bfloat16 g_Xl[(size_t)BATCH*SLEN*EMB];
__device__ __align__(256) __nv_bfloat16 g_Wqh[(size_t)QKVF*EMB];
__device__ __align__(256) __nv_bfloat16 g_Wql[(size_t)QKVF*EMB];
__device__ __align__(256) __nv_bfloat16 g_Woh[(size_t)EMB*EMB];
__device__ __align__(256) __nv_bfloat16 g_Wol[(size_t)EMB*EMB];
__device__ __align__(256) __nv_bfloat16 g_qh[(size_t)BATCH*SLEN*EMB];
__device__ __align__(256) __nv_bfloat16 g_ql[(size_t)BATCH*SLEN*EMB];
__device__ __align__(256) __nv_bfloat16 g_kh[(size_t)BATCH*SLEN*EMB];
__device__ __align__(256) __nv_bfloat16 g_kl[(size_t)BATCH*SLEN*EMB];
__device__ __align__(256) __nv_bfloat16 g_vth[(size_t)BATCH*EMB*SLEN];  // V^T [b,e,s]
__device__ __align__(256) __nv_bfloat16 g_vtl[(size_t)BATCH*EMB*SLEN];
__device__ __align__(256) float         g_att[(size_t)BATCH*SLEN*SLEN];
__device__ __align__(256) __nv_bfloat16 g_ath[(size_t)BATCH*SLEN*SLEN];
__device__ __align__(256) __nv_bfloat16 g_atl[(size_t)BATCH*SLEN*SLEN];
__device__ __align__(256) __nv_bfloat16 g_ch[(size_t)BATCH*SLEN*EMB];
__device__ __align__(256) __nv_bfloat16 g_cl[(size_t)BATCH*SLEN*EMB];

// ---------------------------------------------------------------------------
// PTX helpers (arch-agnostic: sm_80+ features only — tcgen05 is rejected by
// this toolchain's compute_103 PTX target)
// ---------------------------------------------------------------------------
__device__ __forceinline__ uint32_t smem_u32(const void* p) {
    uint32_t a;
    asm("{ .reg .u64 t; cvta.to.shared.u64 t, %1; cvt.u32.u64 %0, t; }"
        : "=r"(a) : "l"(p));
    return a;
}
#define CP16(d, s)   asm volatile("cp.async.cg.shared.global [%0], [%1], 16;" :: "r"(d), "l"(s))
#define CP_COMMIT()  asm volatile("cp.async.commit_group;" ::: "memory")
#define CP_WAIT0()   asm volatile("cp.async.wait_group 0;" ::: "memory")

__device__ __forceinline__ void ldsm4(uint32_t* r, uint32_t addr) {
    asm volatile("ldmatrix.sync.aligned.m8n8.x4.shared.b16 {%0,%1,%2,%3}, [%4];"
        : "=r"(r[0]), "=r"(r[1]), "=r"(r[2]), "=r"(r[3]) : "r"(addr));
}
__device__ __forceinline__ void ldsm2(uint32_t* r, uint32_t addr) {
    asm volatile("ldmatrix.sync.aligned.m8n8.x2.shared.b16 {%0,%1}, [%2];"
        : "=r"(r[0]), "=r"(r[1]) : "r"(addr));
}
__device__ __forceinline__ void mma16816(float* d, const uint32_t* a, const uint32_t* b) {
    asm volatile("mma.sync.aligned.m16n8k16.row.col.f32.bf16.bf16.f32 "
        "{%0,%1,%2,%3}, {%4,%5,%6,%7}, {%8,%9}, {%0,%1,%2,%3};"
        : "+f"(d[0]), "+f"(d[1]), "+f"(d[2]), "+f"(d[3])
        : "r"(a[0]), "r"(a[1]), "r"(a[2]), "r"(a[3]), "r"(b[0]), "r"(b[1]));
}

// Tiling: CTA 128x128, BK=64, 8 warps (2x4), warp tile 64x32.
#define ROWB   144           // 64 bf16 = 128B, padded to 144B (9x16B, conflict-free)
#define TILEB  (128 * ROWB)  // 18432 B per operand tile
#define STAGEB (4 * TILEB)   // Ah, Al, Bh, Bl = 73728 B
#define GEMM_SMEM (2 * STAGEB + 128)

// ---------------------------------------------------------------------------
// bf16x3 GEMM NT:  D[m,n] = alpha * sum_k A[m,k]*B[n,k]   (A,B split hi/lo)
// MODE 0: qkv epilogue (bias; q/k hi-lo row-major; V transposed hi-lo)
// MODE 1: scores       (fp32 out, batched, alpha=1/32)
// MODE 2: ctx          (hi/lo row-major out)
// MODE 3: out proj     (bias; fp32 out)
// ---------------------------------------------------------------------------
template<int MODE>
__global__ void __launch_bounds__(256, 1)
gemm_k(const __nv_bfloat16* __restrict__ Ah, const __nv_bfloat16* __restrict__ Al,
       size_t sA, int ldA,
       const __nv_bfloat16* __restrict__ Bh, const __nv_bfloat16* __restrict__ Bl,
       size_t sB, int ldB, int K,
       float* __restrict__ outF, size_t sF, int ldF,
       __nv_bfloat16* __restrict__ oh0, __nv_bfloat16* __restrict__ ol0,
       __nv_bfloat16* __restrict__ oh1, __nv_bfloat16* __restrict__ ol1,
       __nv_bfloat16* __restrict__ oh2, __nv_bfloat16* __restrict__ ol2,
       const float* __restrict__ bias, float alpha)
{
    extern __shared__ char dsm[];
    const uint32_t sb0 = smem_u32(dsm);
    const uint32_t SB  = (sb0 + 127u) & ~127u;
    float* stg = (float*)(dsm + (SB - sb0));    // epilogue staging [128][132]

    const int tid  = threadIdx.x;
    const int wid  = tid >> 5, lane = tid & 31;
    const int wm   = wid >> 2, wn = wid & 3;    // warp grid 2x4
    const int bx = blockIdx.x, by = blockIdx.y, z = blockIdx.z;

    const char* baseA_h = (const char*)(Ah + (size_t)z * sA + (size_t)by * 128 * ldA);
    const char* baseA_l = (const char*)(Al + (size_t)z * sA + (size_t)by * 128 * ldA);
    const char* baseB_h = (const char*)(Bh + (size_t)z * sB + (size_t)bx * 128 * ldB);
    const char* baseB_l = (const char*)(Bl + (size_t)z * sB + (size_t)bx * 128 * ldB);
    const size_t strA = (size_t)ldA * 2, strB = (size_t)ldB * 2;

    auto load_chunk = [&](int c, int s) {
        const uint32_t stb = SB + (uint32_t)s * STAGEB;
        #pragma unroll
        for (int i = 0; i < 16; i++) {
            const int id = i * 256 + tid;       // 0..4095
            const int t  = id >> 10;            // operand tile 0..3
            const int u  = id & 1023;
            const int r  = u >> 3;              // row 0..127
            const int c16 = u & 7;              // 16B piece 0..7
            const char* base = (t == 0) ? baseA_h : (t == 1) ? baseA_l
                             : (t == 2) ? baseB_h : baseB_l;
            const size_t str = (t < 2) ? strA : strB;
            const char* src = base + (size_t)r * str + (size_t)c * 128 + (size_t)c16 * 16;
            const uint32_t dst = stb + (uint32_t)t * TILEB + (uint32_t)(r * ROWB + c16 * 16);
            CP16(dst, src);
        }
        CP_COMMIT();
    };

    float d[4][4][4];
    #pragma unroll
    for (int a = 0; a < 4; a++)
        #pragma unroll
        for (int b = 0; b < 4; b++)
            #pragma unroll
            for (int e = 0; e < 4; e++) d[a][b][e] = 0.0f;

    const int NC = K >> 6;
    load_chunk(0, 0);

    const int l15 = lane & 15;
    // per-lane ldmatrix address offsets (within a tile, before kk/stage bases)
    const uint32_t offA = (uint32_t)((wm * 64 + (lane & 7) + ((lane >> 3) & 1) * 8) * ROWB
                                     + ((lane >> 4) & 1) * 16);
    const uint32_t offB = (uint32_t)((wn * 32 + (l15 & 7)) * ROWB + (l15 >> 3) * 16);

    for (int c = 0; c < NC; c++) {
        CP_WAIT0();
        __syncthreads();
        const int s = c & 1;
        if (c + 1 < NC) load_chunk(c + 1, s ^ 1);

        const uint32_t stb = SB + (uint32_t)s * STAGEB;
        const uint32_t Ah_s = stb,            Al_s = stb + TILEB;
        const uint32_t Bh_s = stb + 2*TILEB,  Bl_s = stb + 3*TILEB;

        #pragma unroll
        for (int kk = 0; kk < 4; kk++) {
            uint32_t bh[4][2], bl[4][2];
            #pragma unroll
            for (int nt = 0; nt < 4; nt++) {
                const uint32_t o = (uint32_t)(nt * 8 * ROWB) + (uint32_t)(kk * 32) ;
                ldsm2(bh[nt], Bh_s + offB + o);
                ldsm2(bl[nt], Bl_s + offB + o);
            }
            #pragma unroll
            for (int mt = 0; mt < 4; mt++) {
                uint32_t ah[4], al[4];
                const uint32_t o = (uint32_t)(mt * 16 * ROWB) + (uint32_t)(kk * 32);
                ldsm4(ah, Ah_s + offA + o);
                ldsm4(al, Al_s + offA + o);
                #pragma unroll
                for (int nt = 0; nt < 4; nt++) {
                    mma16816(d[mt][nt], ah, bh[nt]);
                    mma16816(d[mt][nt], ah, bl[nt]);
                    mma16816(d[mt][nt], al, bh[nt]);
                }
            }
        }
    }
    __syncthreads();   // all warps done with smem buffers; stg reuses them

    // ---- accumulators -> smem staging (with alpha & bias) ----
    #pragma unroll
    for (int mt = 0; mt < 4; mt++) {
        #pragma unroll
        for (int nt = 0; nt < 4; nt++) {
            const int r0 = wm * 64 + mt * 16 + (lane >> 2);
            const int c0 = wn * 32 + nt * 8 + (lane & 3) * 2;
            #pragma unroll
            for (int h = 0; h < 2; h++) {
                float v0 = d[mt][nt][h * 2 + 0] * alpha;
                float v1 = d[mt][nt][h * 2 + 1] * alpha;
                if (MODE == 0 || MODE == 3) {
                    v0 += bias[bx * 128 + c0];
                    v1 += bias[bx * 128 + c0 + 1];
                }
                float2 vv = make_float2(v0, v1);
                *(float2*)&stg[(r0 + h * 8) * 132 + c0] = vv;
            }
        }
    }
    __syncthreads();

    // ---- MODE-specific writers ----
    if (MODE == 1 || MODE == 3) {
        const int row = tid >> 1, h = tid & 1;
        float* dst = outF + (size_t)z * sF + ((size_t)by * 128 + row) * ldF
                   + (size_t)bx * 128 + h * 64;
        #pragma unroll
        for (int q = 0; q < 16; q++) {
            float4 v;
            v.x = stg[row * 132 + h * 64 + q * 4 + 0];
            v.y = stg[row * 132 + h * 64 + q * 4 + 1];
            v.z = stg[row * 132 + h * 64 + q * 4 + 2];
            v.w = stg[row * 132 + h * 64 + q * 4 + 3];
            ((float4*)dst)[q] = v;
        }
    } else if (MODE == 2 || (MODE == 0 && bx < 16)) {
        __nv_bfloat16 *OH, *OL;
        if (MODE == 2)      { OH = oh0; OL = ol0; }
        else if (bx < 8)    { OH = oh0; OL = ol0; }
        else                { OH = oh1; OL = ol1; }
        #pragma unroll 1
        for (int cb = 0; cb < 4; cb++) {
            #pragma unroll 1
            for (int it = 0; it < 2; it++) {
                const int row = it * 64 + (tid >> 2);
                const int qq  = tid & 3;
                const int col = cb * 32 + qq * 8;
                const size_t rg = (size_t)z * ((size_t)gridDim.y * 128)
                                + (size_t)by * 128 + row;
                const int colE = (MODE == 2) ? (bx * 128 + col) : ((bx & 7) * 128 + col);
                union { __nv_bfloat16 b[8]; uint4 v; } Uh, Ul;
                #pragma unroll
                for (int i = 0; i < 8; i++) {
                    float v = stg[row * 132 + col + i];
                    __nv_bfloat16 hi = __float2bfloat16(v);
                    Uh.b[i] = hi;
                    Ul.b[i] = __float2bfloat16(v - __bfloat162float(hi));
                }
                const size_t off = rg * 1024 + colE;   // FIX: qq*8 already in colE
                *(uint4*)(OH + off) = Uh.v;
                *(uint4*)(OL + off) = Ul.v;
            }
        }
    } else {  // MODE 0, V tiles (bx 16..23): transposed write to vt[b][e][s]
        const int j  = tid >> 3;       // 0..31
        const int rs = tid & 7;        // 16-row segment
        const int bidx = by >> 4;
        const int s0 = (by * 128) & 2047;
        #pragma unroll 1
        for (int cb = 0; cb < 4; cb++) {
            const int col = cb * 32 + j;
            const int colE = (bx & 7) * 128 + col;
            union { __nv_bfloat16 b[16]; uint4 v[2]; } Uh, Ul;
            #pragma unroll
            for (int i = 0; i < 16; i++) {
                float v = stg[(rs * 16 + i) * 132 + col];
                __nv_bfloat16 hi = __float2bfloat16(v);
                Uh.b[i] = hi;
                Ul.b[i] = __float2bfloat16(v - __bfloat162float(hi));
            }
            const size_t off = ((size_t)bidx * 1024 + colE) * 2048 + s0 + rs * 16;
            *(uint4*)(oh2 + off)     = Uh.v[0];
            *(uint4*)(oh2 + off + 8) = Uh.v[1];
            *(uint4*)(ol2 + off)     = Ul.v[0];
            *(uint4*)(ol2 + off + 8) = Ul.v[1];
        }
    }
}

// ---------------------------------------------------------------------------
// fp32 -> bf16 hi/lo split conversion
// ---------------------------------------------------------------------------
__global__ void conv_hl(const float4* __restrict__ x, __nv_bfloat16* __restrict__ h,
                        __nv_bfloat16* __restrict__ l, int n4)
{
    const int i = blockIdx.x * 256 + threadIdx.x;
    if (i >= n4) return;
    const float4 v = x[i];
    const float vv[4] = {v.x, v.y, v.z, v.w};
    union { __nv_bfloat16 b[4]; uint2 u; } H, L;
    #pragma unroll
    for (int k = 0; k < 4; k++) {
        __nv_bfloat16 hi = __float2bfloat16(vv[k]);
        H.b[k] = hi;
        L.b[k] = __float2bfloat16(vv[k] - __bfloat162float(hi));
    }
    *(uint2*)(h + (size_t)i * 4) = H.u;
    *(uint2*)(l + (size_t)i * 4) = L.u;
}

// ---------------------------------------------------------------------------
// Masked softmax over rows of att [8192, 2048]; emits bf16 hi/lo
// ---------------------------------------------------------------------------
__global__ void __launch_bounds__(256)
softmax_k(const float* __restrict__ att, const int* __restrict__ mask,
          __nv_bfloat16* __restrict__ oh, __nv_bfloat16* __restrict__ ol)
{
    const size_t row = blockIdx.x;
    const float* a = att  + row * (size_t)SLEN;
    const int*   m = mask + row * (size_t)SLEN;
    const int tid = threadIdx.x;

    float v[8];
    float lmax = -INFINITY;
    #pragma unroll
    for (int i = 0; i < 8; i++) {
        const int c = tid + i * 256;
        float x = a[c];
        if (m[c] == 0) x = -INFINITY;
        v[i] = x;
        lmax = fmaxf(lmax, x);
    }
    __shared__ float smax[8], ssum[8];
    #pragma unroll
    for (int o = 16; o > 0; o >>= 1)
        lmax = fmaxf(lmax, __shfl_xor_sync(0xffffffffu, lmax, o));
    if ((tid & 31) == 0) smax[tid >> 5] = lmax;
    __syncthreads();
    const float gmax = fmaxf(fmaxf(fmaxf(smax[0], smax[1]), fmaxf(smax[2], smax[3])),
                             fmaxf(fmaxf(smax[4], smax[5]), fmaxf(smax[6], smax[7])));
    float lsum = 0.0f;
    #pragma unroll
    for (int i = 0; i < 8; i++) { v[i] = __expf(v[i] - gmax); lsum += v[i]; }
    #pragma unroll
    for (int o = 16; o > 0; o >>= 1)
        lsum += __shfl_xor_sync(0xffffffffu, lsum, o);
    if ((tid & 31) == 0) ssum[tid >> 5] = lsum;
    __syncthreads();
    const float gsum = (ssum[0] + ssum[1]) + (ssum[2] + ssum[3])
                     + (ssum[4] + ssum[5]) + (ssum[6] + ssum[7]);
    const float inv = 1.0f / gsum;
    #pragma unroll
    for (int i = 0; i < 8; i++) {
        const int c = tid + i * 256;
        const float p = v[i] * inv;
        const __nv_bfloat16 hi = __float2bfloat16(p);
        oh[row * SLEN + c] = hi;
        ol[row * SLEN + c] = __float2bfloat16(p - __bfloat162float(hi));
    }
}

// ---------------------------------------------------------------------------
extern "C" void kernel_launch(void* const* d_in, const int* in_sizes, int n_in,
                              void* d_out, int out_size)
{
    const float* X     = (const float*)d_in[0];
    const int*   mask  = (const int*)  d_in[1];
    const float* W_qkv = (const float*)d_in[2];
    const float* b_qkv = (const float*)d_in[3];
    const float* W_out = (const float*)d_in[4];
    const float* b_out = (const float*)d_in[5];
    float*       out   = (float*)d_out;

    __nv_bfloat16 *Xh, *Xl, *Wqh, *Wql, *Woh, *Wol;
    __nv_bfloat16 *qh, *ql, *kh, *kl, *vth, *vtl, *ath, *atl, *ch, *cl;
    float* att;
    cudaGetSymbolAddress((void**)&Xh,  g_Xh);  cudaGetSymbolAddress((void**)&Xl,  g_Xl);
    cudaGetSymbolAddress((void**)&Wqh, g_Wqh); cudaGetSymbolAddress((void**)&Wql, g_Wql);
    cudaGetSymbolAddress((void**)&Woh, g_Woh); cudaGetSymbolAddress((void**)&Wol, g_Wol);
    cudaGetSymbolAddress((void**)&qh,  g_qh);  cudaGetSymbolAddress((void**)&ql,  g_ql);
    cudaGetSymbolAddress((void**)&kh,  g_kh);  cudaGetSymbolAddress((void**)&kl,  g_kl);
    cudaGetSymbolAddress((void**)&vth, g_vth); cudaGetSymbolAddress((void**)&vtl, g_vtl);
    cudaGetSymbolAddress((void**)&att, g_att);
    cudaGetSymbolAddress((void**)&ath, g_ath); cudaGetSymbolAddress((void**)&atl, g_atl);
    cudaGetSymbolAddress((void**)&ch,  g_ch);  cudaGetSymbolAddress((void**)&cl,  g_cl);

    cudaFuncSetAttribute(gemm_k<0>, cudaFuncAttributeMaxDynamicSharedMemorySize, GEMM_SMEM);
    cudaFuncSetAttribute(gemm_k<1>, cudaFuncAttributeMaxDynamicSharedMemorySize, GEMM_SMEM);
    cudaFuncSetAttribute(gemm_k<2>, cudaFuncAttributeMaxDynamicSharedMemorySize, GEMM_SMEM);
    cudaFuncSetAttribute(gemm_k<3>, cudaFuncAttributeMaxDynamicSharedMemorySize, GEMM_SMEM);

    // Convert inputs to bf16 hi/lo
    conv_hl<<<(BATCH*SLEN*EMB/4 + 255)/256, 256>>>((const float4*)X, Xh, Xl, BATCH*SLEN*EMB/4);
    conv_hl<<<(QKVF*EMB/4 + 255)/256, 256>>>((const float4*)W_qkv, Wqh, Wql, QKVF*EMB/4);
    conv_hl<<<(EMB*EMB/4 + 255)/256, 256>>>((const float4*)W_out, Woh, Wol, EMB*EMB/4);

    // 1) qkv = X @ W_qkv^T + b  -> q/k hi-lo (row-major), V transposed hi-lo
    gemm_k<0><<<dim3(QKVF/128, (BATCH*SLEN)/128, 1), 256, GEMM_SMEM>>>(
        Xh, Xl, 0, EMB, Wqh, Wql, 0, EMB, EMB,
        nullptr, 0, 0, qh, ql, kh, kl, vth, vtl, b_qkv, 1.0f);

    // 2) att = (Q @ K^T) / 32   (fp32 out, per batch)
    gemm_k<1><<<dim3(SLEN/128, SLEN/128, BATCH), 256, GEMM_SMEM>>>(
        qh, ql, (size_t)SLEN*EMB, EMB, kh, kl, (size_t)SLEN*EMB, EMB, EMB,
        att, (size_t)SLEN*SLEN, SLEN,
        nullptr, nullptr, nullptr, nullptr, nullptr, nullptr, nullptr, 0.03125f);

    // 3) masked softmax -> att hi/lo
    softmax_k<<<BATCH*SLEN, 256>>>(att, mask, ath, atl);

    // 4) ctx = att @ V  (B = V^T, NT)  -> ctx hi/lo
    gemm_k<2><<<dim3(EMB/128, SLEN/128, BATCH), 256, GEMM_SMEM>>>(
        ath, atl, (size_t)SLEN*SLEN, SLEN, vth, vtl, (size_t)EMB*SLEN, SLEN, SLEN,
        nullptr, 0, 0, ch, cl, nullptr, nullptr, nullptr, nullptr, nullptr, 1.0f);

    // 5) out = ctx @ W_out^T + b
    gemm_k<3><<<dim3(EMB/128, (BATCH*SLEN)/128, 1), 256, GEMM_SMEM>>>(
        ch, cl, 0, EMB, Woh, Wol, 0, EMB, EMB,
        out, 0, EMB,
        nullptr, nullptr, nullptr, nullptr, nullptr, nullptr, b_out, 1.0f);
}

// round 5
// speedup vs baseline: 2.7303x; 1.0162x over previous
#include <cuda_runtime.h>
#include <cuda_bf16.h>
#include <math.h>
#include <stdint.h>

// Problem constants
#define BATCH 4
#define SLEN  2048
#define EMB   1024
#define QKVF  3072

// ---------------------------------------------------------------------------
// Device scratch (allocation-free rule: __device__ globals)
// ---------------------------------------------------------------------------
__device__ __align__(256) __nv_bfloat16 g_Xh[(size_t)BATCH*SLEN*EMB];
__device__ __align__(256) __nv_bfloat16 g_Xl[(size_t)BATCH*SLEN*EMB];
__device__ __align__(256) __nv_bfloat16 g_Wqh[(size_t)QKVF*EMB];
__device__ __align__(256) __nv_bfloat16 g_Wql[(size_t)QKVF*EMB];
__device__ __align__(256) __nv_bfloat16 g_Woh[(size_t)EMB*EMB];
__device__ __align__(256) __nv_bfloat16 g_Wol[(size_t)EMB*EMB];
__device__ __align__(256) __nv_bfloat16 g_qh[(size_t)BATCH*SLEN*EMB];
__device__ __align__(256) __nv_bfloat16 g_ql[(size_t)BATCH*SLEN*EMB];
__device__ __align__(256) __nv_bfloat16 g_kh[(size_t)BATCH*SLEN*EMB];
__device__ __align__(256) __nv_bfloat16 g_kl[(size_t)BATCH*SLEN*EMB];
__device__ __align__(256) __nv_bfloat16 g_vth[(size_t)BATCH*EMB*SLEN];  // V^T [b,e,s]
__device__ __align__(256) __nv_bfloat16 g_vtl[(size_t)BATCH*EMB*SLEN];
__device__ __align__(256) float         g_att[(size_t)BATCH*SLEN*SLEN];
__device__ __align__(256) __nv_bfloat16 g_ath[(size_t)BATCH*SLEN*SLEN];
__device__ __align__(256) __nv_bfloat16 g_atl[(size_t)BATCH*SLEN*SLEN];
__device__ __align__(256) __nv_bfloat16 g_ch[(size_t)BATCH*SLEN*EMB];
__device__ __align__(256) __nv_bfloat16 g_cl[(size_t)BATCH*SLEN*EMB];

// ---------------------------------------------------------------------------
// PTX helpers (sm_80+ only — tcgen05 rejected by compute_103 PTX target)
// ---------------------------------------------------------------------------
__device__ __forceinline__ uint32_t smem_u32(const void* p) {
    uint32_t a;
    asm("{ .reg .u64 t; cvta.to.shared.u64 t, %1; cvt.u32.u64 %0, t; }"
        : "=r"(a) : "l"(p));
    return a;
}
#define CP16(d, s)   asm volatile("cp.async.cg.shared.global [%0], [%1], 16;" :: "r"(d), "l"(s))
#define CP_COMMIT()  asm volatile("cp.async.commit_group;" ::: "memory")
#define CP_WAIT0()   asm volatile("cp.async.wait_group 0;" ::: "memory")

__device__ __forceinline__ void ldsm4(uint32_t* r, uint32_t addr) {
    asm volatile("ldmatrix.sync.aligned.m8n8.x4.shared.b16 {%0,%1,%2,%3}, [%4];"
        : "=r"(r[0]), "=r"(r[1]), "=r"(r[2]), "=r"(r[3]) : "r"(addr));
}
__device__ __forceinline__ void mma16816(float* d, const uint32_t* a, const uint32_t* b) {
    asm volatile("mma.sync.aligned.m16n8k16.row.col.f32.bf16.bf16.f32 "
        "{%0,%1,%2,%3}, {%4,%5,%6,%7}, {%8,%9}, {%0,%1,%2,%3};"
        : "+f"(d[0]), "+f"(d[1]), "+f"(d[2]), "+f"(d[3])
        : "r"(a[0]), "r"(a[1]), "r"(a[2]), "r"(a[3]), "r"(b[0]), "r"(b[1]));
}

// Tiling: CTA 256x128, BK=64, 8 warps (4x2), warp tile 64x64.
#define ROWB    144                 // 64 bf16 = 128B padded to 144B
#define TILE_A  (256 * ROWB)        // 36864 B  (one of Ah/Al)
#define TILE_B  (128 * ROWB)        // 18432 B  (one of Bh/Bl)
#define STAGEB  (2*TILE_A + 2*TILE_B)   // 110592 B
#define GEMM_SMEM (2 * STAGEB + 128)    // 221312 B

// ---------------------------------------------------------------------------
// bf16x3 GEMM NT:  D[m,n] = alpha * sum_k A[m,k]*B[n,k]   (A,B split hi/lo)
// MODE 0: qkv epilogue (bias; q/k hi-lo row-major; V transposed hi-lo)
// MODE 1: scores       (fp32 out, batched, alpha=1/32)
// MODE 2: ctx          (hi/lo row-major out)
// MODE 3: out proj     (bias; fp32 out)
// ---------------------------------------------------------------------------
template<int MODE>
__global__ void __launch_bounds__(256, 1)
gemm_k(const __nv_bfloat16* __restrict__ Ah, const __nv_bfloat16* __restrict__ Al,
       size_t sA, int ldA,
       const __nv_bfloat16* __restrict__ Bh, const __nv_bfloat16* __restrict__ Bl,
       size_t sB, int ldB, int K,
       float* __restrict__ outF, size_t sF, int ldF,
       __nv_bfloat16* __restrict__ oh0, __nv_bfloat16* __restrict__ ol0,
       __nv_bfloat16* __restrict__ oh1, __nv_bfloat16* __restrict__ ol1,
       __nv_bfloat16* __restrict__ oh2, __nv_bfloat16* __restrict__ ol2,
       const float* __restrict__ bias, float alpha)
{
    extern __shared__ char dsm[];
    const uint32_t sb0 = smem_u32(dsm);
    const uint32_t SB  = (sb0 + 127u) & ~127u;
    float* stg = (float*)(dsm + (SB - sb0));    // epilogue staging [256][132]

    const int tid  = threadIdx.x;
    const int wid  = tid >> 5, lane = tid & 31;
    const int wm   = wid >> 1, wn = wid & 1;    // warp grid 4x2, warp tile 64x64
    const int bx = blockIdx.x, by = blockIdx.y, z = blockIdx.z;

    const char* baseA_h = (const char*)(Ah + (size_t)z * sA + (size_t)by * 256 * ldA);
    const char* baseA_l = (const char*)(Al + (size_t)z * sA + (size_t)by * 256 * ldA);
    const char* baseB_h = (const char*)(Bh + (size_t)z * sB + (size_t)bx * 128 * ldB);
    const char* baseB_l = (const char*)(Bl + (size_t)z * sB + (size_t)bx * 128 * ldB);
    const size_t strA = (size_t)ldA * 2, strB = (size_t)ldB * 2;

    auto load_chunk = [&](int c, int s) {
        const uint32_t stb = SB + (uint32_t)s * STAGEB;
        #pragma unroll
        for (int i = 0; i < 24; i++) {
            const int id = i * 256 + tid;       // 0..6143
            if (id < 4096) {                    // A tiles: hi then lo, 256 rows
                const int t = id >> 11;         // 0=Ah 1=Al
                const int u = id & 2047;
                const int r = u >> 3, c16 = u & 7;
                const char* base = t ? baseA_l : baseA_h;
                const char* src = base + (size_t)r * strA + (size_t)c * 128 + (size_t)c16 * 16;
                const uint32_t dst = stb + (uint32_t)t * TILE_A
                                   + (uint32_t)(r * ROWB + c16 * 16);
                CP16(dst, src);
            } else {                            // B tiles: hi then lo, 128 rows
                const int id2 = id - 4096;
                const int t = id2 >> 10;
                const int u = id2 & 1023;
                const int r = u >> 3, c16 = u & 7;
                const char* base = t ? baseB_l : baseB_h;
                const char* src = base + (size_t)r * strB + (size_t)c * 128 + (size_t)c16 * 16;
                const uint32_t dst = stb + 2u * TILE_A + (uint32_t)t * TILE_B
                                   + (uint32_t)(r * ROWB + c16 * 16);
                CP16(dst, src);
            }
        }
        CP_COMMIT();
    };

    float d[4][8][4];
    #pragma unroll
    for (int a = 0; a < 4; a++)
        #pragma unroll
        for (int b = 0; b < 8; b++)
            #pragma unroll
            for (int e = 0; e < 4; e++) d[a][b][e] = 0.0f;

    const int NC = K >> 6;
    load_chunk(0, 0);

    // A x4: lanes 0-7 rows r0..7 k0 | 8-15 rows 8..15 k0 | 16-23 r0..7 k8 | 24-31 r8..15 k8
    const uint32_t offA = (uint32_t)((wm * 64 + (lane & 7) + ((lane >> 3) & 1) * 8) * ROWB
                                     + ((lane >> 4) & 1) * 16);
    // B x4 paired: m0 rows n0..7 k0 | m1 same rows k8 | m2 rows n8..15 k0 | m3 k8
    const uint32_t offB = (uint32_t)((wn * 64 + ((lane >> 4) & 1) * 8 + (lane & 7)) * ROWB
                                     + ((lane >> 3) & 1) * 16);

    for (int c = 0; c < NC; c++) {
        CP_WAIT0();
        __syncthreads();
        const int s = c & 1;
        if (c + 1 < NC) load_chunk(c + 1, s ^ 1);

        const uint32_t stb = SB + (uint32_t)s * STAGEB;
        const uint32_t Ah_s = stb,              Al_s = stb + TILE_A;
        const uint32_t Bh_s = stb + 2*TILE_A,   Bl_s = stb + 2*TILE_A + TILE_B;

        #pragma unroll
        for (int kk = 0; kk < 4; kk++) {
            uint32_t bh[16], bl[16];
            #pragma unroll
            for (int ntp = 0; ntp < 4; ntp++) {
                const uint32_t o = (uint32_t)(ntp * 16 * ROWB) + (uint32_t)(kk * 32);
                ldsm4(&bh[ntp * 4], Bh_s + offB + o);
                ldsm4(&bl[ntp * 4], Bl_s + offB + o);
            }
            #pragma unroll
            for (int mt = 0; mt < 4; mt++) {
                uint32_t ah[4], al[4];
                const uint32_t o = (uint32_t)(mt * 16 * ROWB) + (uint32_t)(kk * 32);
                ldsm4(ah, Ah_s + offA + o);
                ldsm4(al, Al_s + offA + o);
                #pragma unroll
                for (int nt = 0; nt < 8; nt++) {
                    mma16816(d[mt][nt], ah, &bh[nt * 2]);
                    mma16816(d[mt][nt], ah, &bl[nt * 2]);
                    mma16816(d[mt][nt], al, &bh[nt * 2]);
                }
            }
        }
    }
    __syncthreads();   // all warps done with smem buffers; stg reuses them

    // ---- accumulators -> smem staging (with alpha & bias) ----
    #pragma unroll
    for (int mt = 0; mt < 4; mt++) {
        #pragma unroll
        for (int nt = 0; nt < 8; nt++) {
            const int r0 = wm * 64 + mt * 16 + (lane >> 2);
            const int c0 = wn * 64 + nt * 8 + (lane & 3) * 2;
            #pragma unroll
            for (int h = 0; h < 2; h++) {
                float v0 = d[mt][nt][h * 2 + 0] * alpha;
                float v1 = d[mt][nt][h * 2 + 1] * alpha;
                if (MODE == 0 || MODE == 3) {
                    v0 += bias[bx * 128 + c0];
                    v1 += bias[bx * 128 + c0 + 1];
                }
                float2 vv = make_float2(v0, v1);
                *(float2*)&stg[(r0 + h * 8) * 132 + c0] = vv;
            }
        }
    }
    __syncthreads();

    // ---- MODE-specific writers (256-row tiles) ----
    if (MODE == 1 || MODE == 3) {
        #pragma unroll 1
        for (int rr = 0; rr < 2; rr++) {
            const int row = rr * 128 + (tid >> 1);
            const int h = tid & 1;
            float* dst = outF + (size_t)z * sF + ((size_t)by * 256 + row) * ldF
                       + (size_t)bx * 128 + h * 64;
            #pragma unroll
            for (int q = 0; q < 16; q++) {
                float4 v;
                v.x = stg[row * 132 + h * 64 + q * 4 + 0];
                v.y = stg[row * 132 + h * 64 + q * 4 + 1];
                v.z = stg[row * 132 + h * 64 + q * 4 + 2];
                v.w = stg[row * 132 + h * 64 + q * 4 + 3];
                ((float4*)dst)[q] = v;
            }
        }
    } else if (MODE == 2 || (MODE == 0 && bx < 16)) {
        __nv_bfloat16 *OH, *OL;
        if (MODE == 2)      { OH = oh0; OL = ol0; }
        else if (bx < 8)    { OH = oh0; OL = ol0; }
        else                { OH = oh1; OL = ol1; }
        #pragma unroll 1
        for (int cb = 0; cb < 4; cb++) {
            #pragma unroll 1
            for (int it = 0; it < 4; it++) {
                const int row = it * 64 + (tid >> 2);
                const int qq  = tid & 3;
                const int col = cb * 32 + qq * 8;
                const size_t rg = (size_t)z * ((size_t)gridDim.y * 256)
                                + (size_t)by * 256 + row;
                const int colE = (MODE == 2) ? (bx * 128 + col) : ((bx & 7) * 128 + col);
                union { __nv_bfloat16 b[8]; uint4 v; } Uh, Ul;
                #pragma unroll
                for (int i = 0; i < 8; i++) {
                    float v = stg[row * 132 + col + i];
                    __nv_bfloat16 hi = __float2bfloat16(v);
                    Uh.b[i] = hi;
                    Ul.b[i] = __float2bfloat16(v - __bfloat162float(hi));
                }
                const size_t off = rg * 1024 + colE;
                *(uint4*)(OH + off) = Uh.v;
                *(uint4*)(OL + off) = Ul.v;
            }
        }
    } else {  // MODE 0, V tiles (bx 16..23): transposed write to vt[b][e][s]
        const int j  = tid >> 3;       // col 0..31 within 32-col batch
        const int rs = tid & 7;        // 32-row segment
        const int bidx = by >> 3;      // 2048/256 = 8 tiles per batch
        const int s0 = (by * 256) & 2047;
        #pragma unroll 1
        for (int cb = 0; cb < 4; cb++) {
            const int col = cb * 32 + j;
            const int colE = (bx & 7) * 128 + col;
            union { __nv_bfloat16 b[32]; uint4 v[4]; } Uh, Ul;
            #pragma unroll
            for (int i = 0; i < 32; i++) {
                float v = stg[(rs * 32 + i) * 132 + col];
                __nv_bfloat16 hi = __float2bfloat16(v);
                Uh.b[i] = hi;
                Ul.b[i] = __float2bfloat16(v - __bfloat162float(hi));
            }
            const size_t off = ((size_t)bidx * 1024 + colE) * 2048 + s0 + rs * 32;
            #pragma unroll
            for (int q = 0; q < 4; q++) {
                *(uint4*)(oh2 + off + q * 8) = Uh.v[q];
                *(uint4*)(ol2 + off + q * 8) = Ul.v[q];
            }
        }
    }
}

// ---------------------------------------------------------------------------
// fp32 -> bf16 hi/lo split conversion
// ---------------------------------------------------------------------------
__global__ void conv_hl(const float4* __restrict__ x, __nv_bfloat16* __restrict__ h,
                        __nv_bfloat16* __restrict__ l, int n4)
{
    const int i = blockIdx.x * 256 + threadIdx.x;
    if (i >= n4) return;
    const float4 v = x[i];
    const float vv[4] = {v.x, v.y, v.z, v.w};
    union { __nv_bfloat16 b[4]; uint2 u; } H, L;
    #pragma unroll
    for (int k = 0; k < 4; k++) {
        __nv_bfloat16 hi = __float2bfloat16(vv[k]);
        H.b[k] = hi;
        L.b[k] = __float2bfloat16(vv[k] - __bfloat162float(hi));
    }
    *(uint2*)(h + (size_t)i * 4) = H.u;
    *(uint2*)(l + (size_t)i * 4) = L.u;
}

// ---------------------------------------------------------------------------
// Masked softmax over rows of att [8192, 2048]; emits bf16 hi/lo
// ---------------------------------------------------------------------------
__global__ void __launch_bounds__(256)
softmax_k(const float* __restrict__ att, const int* __restrict__ mask,
          __nv_bfloat16* __restrict__ oh, __nv_bfloat16* __restrict__ ol)
{
    const size_t row = blockIdx.x;
    const float* a = att  + row * (size_t)SLEN;
    const int*   m = mask + row * (size_t)SLEN;
    const int tid = threadIdx.x;

    float v[8];
    float lmax = -INFINITY;
    #pragma unroll
    for (int i = 0; i < 8; i++) {
        const int c = tid + i * 256;
        float x = a[c];
        if (m[c] == 0) x = -INFINITY;
        v[i] = x;
        lmax = fmaxf(lmax, x);
    }
    __shared__ float smax[8], ssum[8];
    #pragma unroll
    for (int o = 16; o > 0; o >>= 1)
        lmax = fmaxf(lmax, __shfl_xor_sync(0xffffffffu, lmax, o));
    if ((tid & 31) == 0) smax[tid >> 5] = lmax;
    __syncthreads();
    const float gmax = fmaxf(fmaxf(fmaxf(smax[0], smax[1]), fmaxf(smax[2], smax[3])),
                             fmaxf(fmaxf(smax[4], smax[5]), fmaxf(smax[6], smax[7])));
    float lsum = 0.0f;
    #pragma unroll
    for (int i = 0; i < 8; i++) { v[i] = __expf(v[i] - gmax); lsum += v[i]; }
    #pragma unroll
    for (int o = 16; o > 0; o >>= 1)
        lsum += __shfl_xor_sync(0xffffffffu, lsum, o);
    if ((tid & 31) == 0) ssum[tid >> 5] = lsum;
    __syncthreads();
    const float gsum = (ssum[0] + ssum[1]) + (ssum[2] + ssum[3])
                     + (ssum[4] + ssum[5]) + (ssum[6] + ssum[7]);
    const float inv = 1.0f / gsum;
    #pragma unroll
    for (int i = 0; i < 8; i++) {
        const int c = tid + i * 256;
        const float p = v[i] * inv;
        const __nv_bfloat16 hi = __float2bfloat16(p);
        oh[row * SLEN + c] = hi;
        ol[row * SLEN + c] = __float2bfloat16(p - __bfloat162float(hi));
    }
}

// ---------------------------------------------------------------------------
extern "C" void kernel_launch(void* const* d_in, const int* in_sizes, int n_in,
                              void* d_out, int out_size)
{
    const float* X     = (const float*)d_in[0];
    const int*   mask  = (const int*)  d_in[1];
    const float* W_qkv = (const float*)d_in[2];
    const float* b_qkv = (const float*)d_in[3];
    const float* W_out = (const float*)d_in[4];
    const float* b_out = (const float*)d_in[5];
    float*       out   = (float*)d_out;

    __nv_bfloat16 *Xh, *Xl, *Wqh, *Wql, *Woh, *Wol;
    __nv_bfloat16 *qh, *ql, *kh, *kl, *vth, *vtl, *ath, *atl, *ch, *cl;
    float* att;
    cudaGetSymbolAddress((void**)&Xh,  g_Xh);  cudaGetSymbolAddress((void**)&Xl,  g_Xl);
    cudaGetSymbolAddress((void**)&Wqh, g_Wqh); cudaGetSymbolAddress((void**)&Wql, g_Wql);
    cudaGetSymbolAddress((void**)&Woh, g_Woh); cudaGetSymbolAddress((void**)&Wol, g_Wol);
    cudaGetSymbolAddress((void**)&qh,  g_qh);  cudaGetSymbolAddress((void**)&ql,  g_ql);
    cudaGetSymbolAddress((void**)&kh,  g_kh);  cudaGetSymbolAddress((void**)&kl,  g_kl);
    cudaGetSymbolAddress((void**)&vth, g_vth); cudaGetSymbolAddress((void**)&vtl, g_vtl);
    cudaGetSymbolAddress((void**)&att, g_att);
    cudaGetSymbolAddress((void**)&ath, g_ath); cudaGetSymbolAddress((void**)&atl, g_atl);
    cudaGetSymbolAddress((void**)&ch,  g_ch);  cudaGetSymbolAddress((void**)&cl,  g_cl);

    cudaFuncSetAttribute(gemm_k<0>, cudaFuncAttributeMaxDynamicSharedMemorySize, GEMM_SMEM);
    cudaFuncSetAttribute(gemm_k<1>, cudaFuncAttributeMaxDynamicSharedMemorySize, GEMM_SMEM);
    cudaFuncSetAttribute(gemm_k<2>, cudaFuncAttributeMaxDynamicSharedMemorySize, GEMM_SMEM);
    cudaFuncSetAttribute(gemm_k<3>, cudaFuncAttributeMaxDynamicSharedMemorySize, GEMM_SMEM);

    // Convert inputs to bf16 hi/lo
    conv_hl<<<(BATCH*SLEN*EMB/4 + 255)/256, 256>>>((const float4*)X, Xh, Xl, BATCH*SLEN*EMB/4);
    conv_hl<<<(QKVF*EMB/4 + 255)/256, 256>>>((const float4*)W_qkv, Wqh, Wql, QKVF*EMB/4);
    conv_hl<<<(EMB*EMB/4 + 255)/256, 256>>>((const float4*)W_out, Woh, Wol, EMB*EMB/4);

    // 1) qkv = X @ W_qkv^T + b  -> q/k hi-lo (row-major), V transposed hi-lo
    gemm_k<0><<<dim3(QKVF/128, (BATCH*SLEN)/256, 1), 256, GEMM_SMEM>>>(
        Xh, Xl, 0, EMB, Wqh, Wql, 0, EMB, EMB,
        nullptr, 0, 0, qh, ql, kh, kl, vth, vtl, b_qkv, 1.0f);

    // 2) att = (Q @ K^T) / 32   (fp32 out, per batch)
    gemm_k<1><<<dim3(SLEN/128, SLEN/256, BATCH), 256, GEMM_SMEM>>>(
        qh, ql, (size_t)SLEN*EMB, EMB, kh, kl, (size_t)SLEN*EMB, EMB, EMB,
        att, (size_t)SLEN*SLEN, SLEN,
        nullptr, nullptr, nullptr, nullptr, nullptr, nullptr, nullptr, 0.03125f);

    // 3) masked softmax -> att hi/lo
    softmax_k<<<BATCH*SLEN, 256>>>(att, mask, ath, atl);

    // 4) ctx = att @ V  (B = V^T, NT)  -> ctx hi/lo
    gemm_k<2><<<dim3(EMB/128, SLEN/256, BATCH), 256, GEMM_SMEM>>>(
        ath, atl, (size_t)SLEN*SLEN, SLEN, vth, vtl, (size_t)EMB*SLEN, SLEN, SLEN,
        nullptr, 0, 0, ch, cl, nullptr, nullptr, nullptr, nullptr, nullptr, 1.0f);

    // 5) out = ctx @ W_out^T + b
    gemm_k<3><<<dim3(EMB/128, (BATCH*SLEN)/256, 1), 256, GEMM_SMEM>>>(
        ch, cl, 0, EMB, Woh, Wol, 0, EMB, EMB,
        out, 0, EMB,
        nullptr, nullptr, nullptr, nullptr, nullptr, nullptr, b_out, 1.0f);
}

// round 6
// speedup vs baseline: 2.7988x; 1.0251x over previous
#include <cuda_runtime.h>
#include <cuda_bf16.h>
#include <math.h>
#include <stdint.h>

// Problem constants
#define BATCH 4
#define SLEN  2048
#define EMB   1024
#define QKVF  3072

// ---------------------------------------------------------------------------
// Device scratch (allocation-free rule: __device__ globals)
// ---------------------------------------------------------------------------
__device__ __align__(256) __nv_bfloat16 g_Xh[(size_t)BATCH*SLEN*EMB];
__device__ __align__(256) __nv_bfloat16 g_Xl[(size_t)BATCH*SLEN*EMB];
__device__ __align__(256) __nv_bfloat16 g_Wqh[(size_t)QKVF*EMB];
__device__ __align__(256) __nv_bfloat16 g_Wql[(size_t)QKVF*EMB];
__device__ __align__(256) __nv_bfloat16 g_Woh[(size_t)EMB*EMB];
__device__ __align__(256) __nv_bfloat16 g_Wol[(size_t)EMB*EMB];
__device__ __align__(256) __nv_bfloat16 g_qh[(size_t)BATCH*SLEN*EMB];
__device__ __align__(256) __nv_bfloat16 g_ql[(size_t)BATCH*SLEN*EMB];
__device__ __align__(256) __nv_bfloat16 g_kh[(size_t)BATCH*SLEN*EMB];
__device__ __align__(256) __nv_bfloat16 g_kl[(size_t)BATCH*SLEN*EMB];
__device__ __align__(256) __nv_bfloat16 g_vth[(size_t)BATCH*EMB*SLEN];  // V^T [b,e,s]
__device__ __align__(256) __nv_bfloat16 g_vtl[(size_t)BATCH*EMB*SLEN];
__device__ __align__(256) float         g_att[(size_t)BATCH*SLEN*SLEN];
__device__ __align__(256) __nv_bfloat16 g_ath[(size_t)BATCH*SLEN*SLEN];
__device__ __align__(256) __nv_bfloat16 g_atl[(size_t)BATCH*SLEN*SLEN];
__device__ __align__(256) __nv_bfloat16 g_ch[(size_t)BATCH*SLEN*EMB];
__device__ __align__(256) __nv_bfloat16 g_cl[(size_t)BATCH*SLEN*EMB];

// ---------------------------------------------------------------------------
// PTX helpers (sm_80+ only — tcgen05 rejected by compute_103 PTX target)
// ---------------------------------------------------------------------------
__device__ __forceinline__ uint32_t smem_u32(const void* p) {
    uint32_t a;
    asm("{ .reg .u64 t; cvta.to.shared.u64 t, %1; cvt.u32.u64 %0, t; }"
        : "=r"(a) : "l"(p));
    return a;
}
#define CP16(d, s)   asm volatile("cp.async.cg.shared.global [%0], [%1], 16;" :: "r"(d), "l"(s))
#define CP_COMMIT()  asm volatile("cp.async.commit_group;" ::: "memory")
#define CP_WAIT0()   asm volatile("cp.async.wait_group 0;" ::: "memory")

__device__ __forceinline__ void ldsm4(uint32_t* r, uint32_t addr) {
    asm volatile("ldmatrix.sync.aligned.m8n8.x4.shared.b16 {%0,%1,%2,%3}, [%4];"
        : "=r"(r[0]), "=r"(r[1]), "=r"(r[2]), "=r"(r[3]) : "r"(addr));
}
__device__ __forceinline__ void mma16816(float* d, const uint32_t* a, const uint32_t* b) {
    asm volatile("mma.sync.aligned.m16n8k16.row.col.f32.bf16.bf16.f32 "
        "{%0,%1,%2,%3}, {%4,%5,%6,%7}, {%8,%9}, {%0,%1,%2,%3};"
        : "+f"(d[0]), "+f"(d[1]), "+f"(d[2]), "+f"(d[3])
        : "r"(a[0]), "r"(a[1]), "r"(a[2]), "r"(a[3]), "r"(b[0]), "r"(b[1]));
}

// Tiling: CTA 128x128, BK=32, 8 warps (2x4), warp tile 64x32. 2 CTAs/SM.
#define ROWB    80                  // 32 bf16 = 64B padded to 80B (16B-aligned rows,
                                    // stride 20 banks -> conflict-free 8-row ldmatrix)
#define TILEB   (128 * ROWB)        // 10240 B per operand tile
#define STAGEB  (4 * TILEB)         // Ah, Al, Bh, Bl = 40960 B
#define GEMM_SMEM (2 * STAGEB + 128)    // 82048 B -> 2 CTAs/SM

// ---------------------------------------------------------------------------
// bf16x3 GEMM NT:  D[m,n] = alpha * sum_k A[m,k]*B[n,k]   (A,B split hi/lo)
// MODE 0: qkv epilogue (bias; q/k hi-lo row-major; V transposed hi-lo)
// MODE 1: scores       (fp32 out, batched, alpha=1/32)
// MODE 2: ctx          (hi/lo row-major out)
// MODE 3: out proj     (bias; fp32 out)
// ---------------------------------------------------------------------------
template<int MODE>
__global__ void __launch_bounds__(256, 2)
gemm_k(const __nv_bfloat16* __restrict__ Ah, const __nv_bfloat16* __restrict__ Al,
       size_t sA, int ldA,
       const __nv_bfloat16* __restrict__ Bh, const __nv_bfloat16* __restrict__ Bl,
       size_t sB, int ldB, int K,
       float* __restrict__ outF, size_t sF, int ldF,
       __nv_bfloat16* __restrict__ oh0, __nv_bfloat16* __restrict__ ol0,
       __nv_bfloat16* __restrict__ oh1, __nv_bfloat16* __restrict__ ol1,
       __nv_bfloat16* __restrict__ oh2, __nv_bfloat16* __restrict__ ol2,
       const float* __restrict__ bias, float alpha)
{
    extern __shared__ char dsm[];
    const uint32_t sb0 = smem_u32(dsm);
    const uint32_t SB  = (sb0 + 127u) & ~127u;
    float* stg = (float*)(dsm + (SB - sb0));    // epilogue staging [128][132]

    const int tid  = threadIdx.x;
    const int wid  = tid >> 5, lane = tid & 31;
    const int wm   = wid >> 2, wn = wid & 3;    // warp grid 2x4, warp tile 64x32
    const int bx = blockIdx.x, by = blockIdx.y, z = blockIdx.z;

    const char* baseA_h = (const char*)(Ah + (size_t)z * sA + (size_t)by * 128 * ldA);
    const char* baseA_l = (const char*)(Al + (size_t)z * sA + (size_t)by * 128 * ldA);
    const char* baseB_h = (const char*)(Bh + (size_t)z * sB + (size_t)bx * 128 * ldB);
    const char* baseB_l = (const char*)(Bl + (size_t)z * sB + (size_t)bx * 128 * ldB);
    const size_t strA = (size_t)ldA * 2, strB = (size_t)ldB * 2;

    auto load_chunk = [&](int c, int s) {
        const uint32_t stb = SB + (uint32_t)s * STAGEB;
        #pragma unroll
        for (int i = 0; i < 8; i++) {
            const int id = i * 256 + tid;       // 0..2047
            const int t  = id >> 9;             // operand tile 0..3
            const int u  = id & 511;
            const int r  = u >> 2;              // row 0..127
            const int c16 = u & 3;              // 16B piece 0..3
            const char* base = (t == 0) ? baseA_h : (t == 1) ? baseA_l
                             : (t == 2) ? baseB_h : baseB_l;
            const size_t str = (t < 2) ? strA : strB;
            const char* src = base + (size_t)r * str + (size_t)c * 64 + (size_t)c16 * 16;
            const uint32_t dst = stb + (uint32_t)t * TILEB + (uint32_t)(r * ROWB + c16 * 16);
            CP16(dst, src);
        }
        CP_COMMIT();
    };

    float d[4][4][4];
    #pragma unroll
    for (int a = 0; a < 4; a++)
        #pragma unroll
        for (int b = 0; b < 4; b++)
            #pragma unroll
            for (int e = 0; e < 4; e++) d[a][b][e] = 0.0f;

    const int NC = K >> 5;
    load_chunk(0, 0);

    // A x4: lanes 0-7 rows m0..7 k0 | 8-15 m8..15 k0 | 16-23 m0..7 k8 | 24-31 m8..15 k8
    const uint32_t offA = (uint32_t)((wm * 64 + (lane & 7) + ((lane >> 3) & 1) * 8) * ROWB
                                     + ((lane >> 4) & 1) * 16);
    // B x4 paired (16 n-cols per load): lanes 0-7 n0..7 k0 | 8-15 n0..7 k8
    //                                   | 16-23 n8..15 k0 | 24-31 n8..15 k8
    const uint32_t offB = (uint32_t)((wn * 32 + ((lane >> 4) & 1) * 8 + (lane & 7)) * ROWB
                                     + ((lane >> 3) & 1) * 16);

    for (int c = 0; c < NC; c++) {
        CP_WAIT0();
        __syncthreads();
        const int s = c & 1;
        if (c + 1 < NC) load_chunk(c + 1, s ^ 1);

        const uint32_t stb = SB + (uint32_t)s * STAGEB;
        const uint32_t Ah_s = stb,            Al_s = stb + TILEB;
        const uint32_t Bh_s = stb + 2*TILEB,  Bl_s = stb + 3*TILEB;

        #pragma unroll
        for (int kk = 0; kk < 2; kk++) {
            uint32_t bh[8], bl[8];
            ldsm4(&bh[0], Bh_s + offB + (uint32_t)(kk * 32));
            ldsm4(&bh[4], Bh_s + offB + (uint32_t)(16 * ROWB + kk * 32));
            ldsm4(&bl[0], Bl_s + offB + (uint32_t)(kk * 32));
            ldsm4(&bl[4], Bl_s + offB + (uint32_t)(16 * ROWB + kk * 32));
            #pragma unroll
            for (int mt = 0; mt < 4; mt++) {
                uint32_t ah[4], al[4];
                const uint32_t o = (uint32_t)(mt * 16 * ROWB) + (uint32_t)(kk * 32);
                ldsm4(ah, Ah_s + offA + o);
                ldsm4(al, Al_s + offA + o);
                #pragma unroll
                for (int nt = 0; nt < 4; nt++) {
                    mma16816(d[mt][nt], ah, &bh[nt * 2]);
                    mma16816(d[mt][nt], ah, &bl[nt * 2]);
                    mma16816(d[mt][nt], al, &bh[nt * 2]);
                }
            }
        }
    }
    __syncthreads();   // all warps done with smem buffers; stg reuses them

    // ---- accumulators -> smem staging (with alpha & bias) ----
    #pragma unroll
    for (int mt = 0; mt < 4; mt++) {
        #pragma unroll
        for (int nt = 0; nt < 4; nt++) {
            const int r0 = wm * 64 + mt * 16 + (lane >> 2);
            const int c0 = wn * 32 + nt * 8 + (lane & 3) * 2;
            #pragma unroll
            for (int h = 0; h < 2; h++) {
                float v0 = d[mt][nt][h * 2 + 0] * alpha;
                float v1 = d[mt][nt][h * 2 + 1] * alpha;
                if (MODE == 0 || MODE == 3) {
                    v0 += bias[bx * 128 + c0];
                    v1 += bias[bx * 128 + c0 + 1];
                }
                float2 vv = make_float2(v0, v1);
                *(float2*)&stg[(r0 + h * 8) * 132 + c0] = vv;
            }
        }
    }
    __syncthreads();

    // ---- MODE-specific writers ----
    if (MODE == 1 || MODE == 3) {
        const int row = tid >> 1, h = tid & 1;
        float* dst = outF + (size_t)z * sF + ((size_t)by * 128 + row) * ldF
                   + (size_t)bx * 128 + h * 64;
        #pragma unroll
        for (int q = 0; q < 16; q++) {
            float4 v;
            v.x = stg[row * 132 + h * 64 + q * 4 + 0];
            v.y = stg[row * 132 + h * 64 + q * 4 + 1];
            v.z = stg[row * 132 + h * 64 + q * 4 + 2];
            v.w = stg[row * 132 + h * 64 + q * 4 + 3];
            ((float4*)dst)[q] = v;
        }
    } else if (MODE == 2 || (MODE == 0 && bx < 16)) {
        __nv_bfloat16 *OH, *OL;
        if (MODE == 2)      { OH = oh0; OL = ol0; }
        else if (bx < 8)    { OH = oh0; OL = ol0; }
        else                { OH = oh1; OL = ol1; }
        #pragma unroll 1
        for (int cb = 0; cb < 4; cb++) {
            #pragma unroll 1
            for (int it = 0; it < 2; it++) {
                const int row = it * 64 + (tid >> 2);
                const int qq  = tid & 3;
                const int col = cb * 32 + qq * 8;
                const size_t rg = (size_t)z * ((size_t)gridDim.y * 128)
                                + (size_t)by * 128 + row;
                const int colE = (MODE == 2) ? (bx * 128 + col) : ((bx & 7) * 128 + col);
                union { __nv_bfloat16 b[8]; uint4 v; } Uh, Ul;
                #pragma unroll
                for (int i = 0; i < 8; i++) {
                    float v = stg[row * 132 + col + i];
                    __nv_bfloat16 hi = __float2bfloat16(v);
                    Uh.b[i] = hi;
                    Ul.b[i] = __float2bfloat16(v - __bfloat162float(hi));
                }
                const size_t off = rg * 1024 + colE;
                *(uint4*)(OH + off) = Uh.v;
                *(uint4*)(OL + off) = Ul.v;
            }
        }
    } else {  // MODE 0, V tiles (bx 16..23): transposed write to vt[b][e][s]
        const int j  = tid >> 3;       // 0..31
        const int rs = tid & 7;        // 16-row segment
        const int bidx = by >> 4;
        const int s0 = (by * 128) & 2047;
        #pragma unroll 1
        for (int cb = 0; cb < 4; cb++) {
            const int col = cb * 32 + j;
            const int colE = (bx & 7) * 128 + col;
            union { __nv_bfloat16 b[16]; uint4 v[2]; } Uh, Ul;
            #pragma unroll
            for (int i = 0; i < 16; i++) {
                float v = stg[(rs * 16 + i) * 132 + col];
                __nv_bfloat16 hi = __float2bfloat16(v);
                Uh.b[i] = hi;
                Ul.b[i] = __float2bfloat16(v - __bfloat162float(hi));
            }
            const size_t off = ((size_t)bidx * 1024 + colE) * 2048 + s0 + rs * 16;
            *(uint4*)(oh2 + off)     = Uh.v[0];
            *(uint4*)(oh2 + off + 8) = Uh.v[1];
            *(uint4*)(ol2 + off)     = Ul.v[0];
            *(uint4*)(ol2 + off + 8) = Ul.v[1];
        }
    }
}

// ---------------------------------------------------------------------------
// fp32 -> bf16 hi/lo split conversion
// ---------------------------------------------------------------------------
__global__ void conv_hl(const float4* __restrict__ x, __nv_bfloat16* __restrict__ h,
                        __nv_bfloat16* __restrict__ l, int n4)
{
    const int i = blockIdx.x * 256 + threadIdx.x;
    if (i >= n4) return;
    const float4 v = x[i];
    const float vv[4] = {v.x, v.y, v.z, v.w};
    union { __nv_bfloat16 b[4]; uint2 u; } H, L;
    #pragma unroll
    for (int k = 0; k < 4; k++) {
        __nv_bfloat16 hi = __float2bfloat16(vv[k]);
        H.b[k] = hi;
        L.b[k] = __float2bfloat16(vv[k] - __bfloat162float(hi));
    }
    *(uint2*)(h + (size_t)i * 4) = H.u;
    *(uint2*)(l + (size_t)i * 4) = L.u;
}

// ---------------------------------------------------------------------------
// Masked softmax over rows of att [8192, 2048]; emits bf16 hi/lo
// ---------------------------------------------------------------------------
__global__ void __launch_bounds__(256)
softmax_k(const float* __restrict__ att, const int* __restrict__ mask,
          __nv_bfloat16* __restrict__ oh, __nv_bfloat16* __restrict__ ol)
{
    const size_t row = blockIdx.x;
    const float* a = att  + row * (size_t)SLEN;
    const int*   m = mask + row * (size_t)SLEN;
    const int tid = threadIdx.x;

    float v[8];
    float lmax = -INFINITY;
    #pragma unroll
    for (int i = 0; i < 8; i++) {
        const int c = tid + i * 256;
        float x = a[c];
        if (m[c] == 0) x = -INFINITY;
        v[i] = x;
        lmax = fmaxf(lmax, x);
    }
    __shared__ float smax[8], ssum[8];
    #pragma unroll
    for (int o = 16; o > 0; o >>= 1)
        lmax = fmaxf(lmax, __shfl_xor_sync(0xffffffffu, lmax, o));
    if ((tid & 31) == 0) smax[tid >> 5] = lmax;
    __syncthreads();
    const float gmax = fmaxf(fmaxf(fmaxf(smax[0], smax[1]), fmaxf(smax[2], smax[3])),
                             fmaxf(fmaxf(smax[4], smax[5]), fmaxf(smax[6], smax[7])));
    float lsum = 0.0f;
    #pragma unroll
    for (int i = 0; i < 8; i++) { v[i] = __expf(v[i] - gmax); lsum += v[i]; }
    #pragma unroll
    for (int o = 16; o > 0; o >>= 1)
        lsum += __shfl_xor_sync(0xffffffffu, lsum, o);
    if ((tid & 31) == 0) ssum[tid >> 5] = lsum;
    __syncthreads();
    const float gsum = (ssum[0] + ssum[1]) + (ssum[2] + ssum[3])
                     + (ssum[4] + ssum[5]) + (ssum[6] + ssum[7]);
    const float inv = 1.0f / gsum;
    #pragma unroll
    for (int i = 0; i < 8; i++) {
        const int c = tid + i * 256;
        const float p = v[i] * inv;
        const __nv_bfloat16 hi = __float2bfloat16(p);
        oh[row * SLEN + c] = hi;
        ol[row * SLEN + c] = __float2bfloat16(p - __bfloat162float(hi));
    }
}

// ---------------------------------------------------------------------------
extern "C" void kernel_launch(void* const* d_in, const int* in_sizes, int n_in,
                              void* d_out, int out_size)
{
    const float* X     = (const float*)d_in[0];
    const int*   mask  = (const int*)  d_in[1];
    const float* W_qkv = (const float*)d_in[2];
    const float* b_qkv = (const float*)d_in[3];
    const float* W_out = (const float*)d_in[4];
    const float* b_out = (const float*)d_in[5];
    float*       out   = (float*)d_out;

    __nv_bfloat16 *Xh, *Xl, *Wqh, *Wql, *Woh, *Wol;
    __nv_bfloat16 *qh, *ql, *kh, *kl, *vth, *vtl, *ath, *atl, *ch, *cl;
    float* att;
    cudaGetSymbolAddress((void**)&Xh,  g_Xh);  cudaGetSymbolAddress((void**)&Xl,  g_Xl);
    cudaGetSymbolAddress((void**)&Wqh, g_Wqh); cudaGetSymbolAddress((void**)&Wql, g_Wql);
    cudaGetSymbolAddress((void**)&Woh, g_Woh); cudaGetSymbolAddress((void**)&Wol, g_Wol);
    cudaGetSymbolAddress((void**)&qh,  g_qh);  cudaGetSymbolAddress((void**)&ql,  g_ql);
    cudaGetSymbolAddress((void**)&kh,  g_kh);  cudaGetSymbolAddress((void**)&kl,  g_kl);
    cudaGetSymbolAddress((void**)&vth, g_vth); cudaGetSymbolAddress((void**)&vtl, g_vtl);
    cudaGetSymbolAddress((void**)&att, g_att);
    cudaGetSymbolAddress((void**)&ath, g_ath); cudaGetSymbolAddress((void**)&atl, g_atl);
    cudaGetSymbolAddress((void**)&ch,  g_ch);  cudaGetSymbolAddress((void**)&cl,  g_cl);

    cudaFuncSetAttribute(gemm_k<0>, cudaFuncAttributeMaxDynamicSharedMemorySize, GEMM_SMEM);
    cudaFuncSetAttribute(gemm_k<1>, cudaFuncAttributeMaxDynamicSharedMemorySize, GEMM_SMEM);
    cudaFuncSetAttribute(gemm_k<2>, cudaFuncAttributeMaxDynamicSharedMemorySize, GEMM_SMEM);
    cudaFuncSetAttribute(gemm_k<3>, cudaFuncAttributeMaxDynamicSharedMemorySize, GEMM_SMEM);

    // Convert inputs to bf16 hi/lo
    conv_hl<<<(BATCH*SLEN*EMB/4 + 255)/256, 256>>>((const float4*)X, Xh, Xl, BATCH*SLEN*EMB/4);
    conv_hl<<<(QKVF*EMB/4 + 255)/256, 256>>>((const float4*)W_qkv, Wqh, Wql, QKVF*EMB/4);
    conv_hl<<<(EMB*EMB/4 + 255)/256, 256>>>((const float4*)W_out, Woh, Wol, EMB*EMB/4);

    // 1) qkv = X @ W_qkv^T + b  -> q/k hi-lo (row-major), V transposed hi-lo
    gemm_k<0><<<dim3(QKVF/128, (BATCH*SLEN)/128, 1), 256, GEMM_SMEM>>>(
        Xh, Xl, 0, EMB, Wqh, Wql, 0, EMB, EMB,
        nullptr, 0, 0, qh, ql, kh, kl, vth, vtl, b_qkv, 1.0f);

    // 2) att = (Q @ K^T) / 32   (fp32 out, per batch)
    gemm_k<1><<<dim3(SLEN/128, SLEN/128, BATCH), 256, GEMM_SMEM>>>(
        qh, ql, (size_t)SLEN*EMB, EMB, kh, kl, (size_t)SLEN*EMB, EMB, EMB,
        att, (size_t)SLEN*SLEN, SLEN,
        nullptr, nullptr, nullptr, nullptr, nullptr, nullptr, nullptr, 0.03125f);

    // 3) masked softmax -> att hi/lo
    softmax_k<<<BATCH*SLEN, 256>>>(att, mask, ath, atl);

    // 4) ctx = att @ V  (B = V^T, NT)  -> ctx hi/lo
    gemm_k<2><<<dim3(EMB/128, SLEN/128, BATCH), 256, GEMM_SMEM>>>(
        ath, atl, (size_t)SLEN*SLEN, SLEN, vth, vtl, (size_t)EMB*SLEN, SLEN, SLEN,
        nullptr, 0, 0, ch, cl, nullptr, nullptr, nullptr, nullptr, nullptr, 1.0f);

    // 5) out = ctx @ W_out^T + b
    gemm_k<3><<<dim3(EMB/128, (BATCH*SLEN)/128, 1), 256, GEMM_SMEM>>>(
        ch, cl, 0, EMB, Woh, Wol, 0, EMB, EMB,
        out, 0, EMB,
        nullptr, nullptr, nullptr, nullptr, nullptr, nullptr, b_out, 1.0f);
}